// round 11
// baseline (speedup 1.0000x reference)
#include <cuda_runtime.h>
#include <cuda_bf16.h>
#include <cstdint>

// out = x @ Weff + bias;  Weff[8m+p, f] = sum_k scale[k,f]*sign(bit(7-p) of binary[k,m,f])
// Persistent kernel, grid = #SMs, 512 threads (16 warps). 3 phases, grid barriers:
//   P1: fold binary*scale -> bf16 hi/lo Weff^T ([f][k]); split x -> Ah/Al
//   P2: 144 jobs (12 f-tiles x 2 m-tiles x 6 k-splits), tile 128m x 64f x 128k,
//       fused 3-segment HMMA (Ah*Bh + Al*Bh + Ah*Bl) -> g_part
//   P3: distributed reduce: 6 partials + bias -> out

#define NX 768
#define NF 768
#define NM 256
#define NG 96

#define SPLITS 6
#define KC 128
#define JOBS 144         // 12 * 2 * 6
#define ROWP 136         // 128 + 8 halves pad -> conflict-free ldmatrix

__device__ __nv_bfloat16 g_ah[NM * NX];
__device__ __nv_bfloat16 g_al[NM * NX];
__device__ __nv_bfloat16 g_bh[NF * NX];   // [f][k]
__device__ __nv_bfloat16 g_bl[NF * NX];
__device__ float    g_part[SPLITS * NM * NF];
__device__ unsigned g_bar;                // monotonic ticket barrier (never reset)

// ---------------------------------------------------------------------------
union B2U { __nv_bfloat162 h2; uint32_t u; };
__device__ __forceinline__ uint32_t pk2(__nv_bfloat16 a, __nv_bfloat16 b) {
    B2U t; t.h2 = __halves2bfloat162(a, b); return t.u;
}
__device__ __forceinline__ uint32_t smem_u32(const void* p) {
    uint32_t a;
    asm("{ .reg .u64 t; cvta.to.shared.u64 t, %1; cvt.u32.u64 %0, t; }"
        : "=r"(a) : "l"(p));
    return a;
}
__device__ __forceinline__ void cp16(uint32_t s, const void* g) {
    asm volatile("cp.async.cg.shared.global [%0], [%1], 16;" :: "r"(s), "l"(g));
}

#define LDSM4(r, addr) \
    asm volatile("ldmatrix.sync.aligned.m8n8.x4.shared.b16 {%0,%1,%2,%3}, [%4];" \
                 : "=r"((r)[0]), "=r"((r)[1]), "=r"((r)[2]), "=r"((r)[3]) : "r"(addr))

#define MMA16816(c, a, bb0, bb1) \
    asm volatile("mma.sync.aligned.m16n8k16.row.col.f32.bf16.bf16.f32 " \
                 "{%0,%1,%2,%3}, {%4,%5,%6,%7}, {%8,%9}, {%0,%1,%2,%3};" \
                 : "+f"((c)[0]), "+f"((c)[1]), "+f"((c)[2]), "+f"((c)[3]) \
                 : "r"((a)[0]), "r"((a)[1]), "r"((a)[2]), "r"((a)[3]), \
                   "r"(bb0), "r"(bb1))

// Adaptive grid barrier; ticket-derived target -> self-advancing, replay-safe.
__device__ __forceinline__ void grid_bar() {
    __syncthreads();
    if (threadIdx.x == 0) {
        __threadfence();
        const unsigned nb = gridDim.x;
        unsigned my = atomicAdd(&g_bar, 1u);
        unsigned target = (my / nb + 1u) * nb;
        unsigned v;
        do {
            __nanosleep(32);
            asm volatile("ld.acquire.gpu.global.u32 %0, [%1];" : "=r"(v) : "l"(&g_bar));
        } while ((int)(v - target) < 0);
        __threadfence();
    }
    __syncthreads();
}

// ---------------------------------------------------------------------------
// smem layout (halves): AH[128*ROWP], AL[128*ROWP], BH[64*ROWP], BL[64*ROWP]
#define SM_AT (128 * ROWP)           // 17408
#define SM_BT (64 * ROWP)            // 8704
#define OFF_AH 0
#define OFF_AL SM_AT
#define OFF_BH (2 * SM_AT)
#define OFF_BL (2 * SM_AT + SM_BT)
#define SMEM_BYTES ((2 * SM_AT + 2 * SM_BT) * 2)   // 104448

__global__ __launch_bounds__(512)
void fused_kernel(const float* __restrict__ x,
                  const float* __restrict__ scale,
                  const int*   __restrict__ binary,
                  const float* __restrict__ bias,
                  float*       __restrict__ out) {
    extern __shared__ __align__(16) __nv_bfloat16 sm[];
    const int tid = threadIdx.x;
    const int cta = blockIdx.x;
    const int NT  = gridDim.x * 512;
    const int tg  = cta * 512 + tid;

    // ================= Phase 1: prep =================
    for (int t = tg; t < NG * NF; t += NT) {       // build Bh/Bl (1 item/thread)
        const int f = t % NF;
        const int m = t / NF;

        int   c[8];
        float s[8];
#pragma unroll
        for (int k = 0; k < 8; k++) {
            c[k] = binary[(k * NG + m) * NF + f];
            s[k] = scale[k * NF + f];
        }
        float w[8];
#pragma unroll
        for (int p = 0; p < 8; p++) w[p] = 0.0f;
#pragma unroll
        for (int k = 0; k < 8; k++)
#pragma unroll
            for (int p = 0; p < 8; p++)
                w[p] += ((c[k] >> (7 - p)) & 1) ? s[k] : -s[k];

        __nv_bfloat16 hi[8], lo[8];
#pragma unroll
        for (int p = 0; p < 8; p++) {
            hi[p] = __float2bfloat16(w[p]);
            lo[p] = __float2bfloat16(w[p] - __bfloat162float(hi[p]));
        }
        *(uint4*)(g_bh + (size_t)f * NX + 8 * m) =
            make_uint4(pk2(hi[0], hi[1]), pk2(hi[2], hi[3]),
                       pk2(hi[4], hi[5]), pk2(hi[6], hi[7]));
        *(uint4*)(g_bl + (size_t)f * NX + 8 * m) =
            make_uint4(pk2(lo[0], lo[1]), pk2(lo[2], lo[3]),
                       pk2(lo[4], lo[5]), pk2(lo[6], lo[7]));
    }
    for (int i = tg; i < NM * NX / 4; i += NT) {   // split x -> Ah/Al
        float4 v = ((const float4*)x)[i];
        __nv_bfloat16 h0 = __float2bfloat16(v.x), h1 = __float2bfloat16(v.y);
        __nv_bfloat16 h2 = __float2bfloat16(v.z), h3 = __float2bfloat16(v.w);
        __nv_bfloat16 l0 = __float2bfloat16(v.x - __bfloat162float(h0));
        __nv_bfloat16 l1 = __float2bfloat16(v.y - __bfloat162float(h1));
        __nv_bfloat16 l2 = __float2bfloat16(v.z - __bfloat162float(h2));
        __nv_bfloat16 l3 = __float2bfloat16(v.w - __bfloat162float(h3));
        ((uint2*)g_ah)[i] = make_uint2(pk2(h0, h1), pk2(h2, h3));
        ((uint2*)g_al)[i] = make_uint2(pk2(l0, l1), pk2(l2, l3));
    }

    grid_bar();

    // ================= Phase 2: GEMM =================
    {
        const uint32_t smb = smem_u32(sm);
        const int wid  = tid >> 5;
        const int lane = tid & 31;
        const int wm = (wid >> 1) * 16;   // 8 m-warps
        const int wn = (wid & 1) * 32;    // 2 f-warps

        for (int job = cta; job < JOBS; job += gridDim.x) {
            const int fx = job % 12;
            const int my = (job / 12) % 2;
            const int kz = job / 24;          // 0..5

            const int f0 = fx * 64;
            const int m0 = my * 128;
            const int kb = kz * KC;

            const __nv_bfloat16* gAH = g_ah + (size_t)m0 * NX + kb;
            const __nv_bfloat16* gAL = g_al + (size_t)m0 * NX + kb;
            const __nv_bfloat16* gBH = g_bh + (size_t)f0 * NX + kb;
            const __nv_bfloat16* gBL = g_bl + (size_t)f0 * NX + kb;

            // A tiles: 128 rows x 128 cols -> 2048 cp16 each
#pragma unroll
            for (int j = 0; j < 4; j++) {
                int idx = tid + 512 * j;              // 0..2047
                int rr = idx >> 4, c8 = (idx & 15) * 8;
                size_t go = (size_t)rr * NX + c8;
                uint32_t so = smb + (uint32_t)(rr * ROWP + c8) * 2;
                cp16(so + OFF_AH * 2, gAH + go);
                cp16(so + OFF_AL * 2, gAL + go);
            }
            // B tiles: 64 rows x 128 cols -> 1024 cp16 each
#pragma unroll
            for (int j = 0; j < 2; j++) {
                int idx = tid + 512 * j;              // 0..1023
                int rr = idx >> 4, c8 = (idx & 15) * 8;
                size_t go = (size_t)rr * NX + c8;
                uint32_t so = smb + (uint32_t)(rr * ROWP + c8) * 2;
                cp16(so + OFF_BH * 2, gBH + go);
                cp16(so + OFF_BL * 2, gBL + go);
            }
            asm volatile("cp.async.commit_group;" ::: "memory");

            float acc[4][4];
#pragma unroll
            for (int j = 0; j < 4; j++)
#pragma unroll
                for (int v = 0; v < 4; v++) acc[j][v] = 0.0f;

            asm volatile("cp.async.wait_group 0;" ::: "memory");
            __syncthreads();

            const int ra  = wm + (lane & 15);
            const int rb0 = wn + (lane & 15);

#pragma unroll
            for (int ks = 0; ks < 8; ks++) {
                const int c = ks * 16 + ((lane >> 4) << 3);
                uint32_t ah[4], al[4], bh0[4], bh1[4], bl0[4], bl1[4];
                LDSM4(ah,  smb + (uint32_t)(OFF_AH + ra * ROWP + c) * 2);
                LDSM4(al,  smb + (uint32_t)(OFF_AL + ra * ROWP + c) * 2);
                LDSM4(bh0, smb + (uint32_t)(OFF_BH + rb0 * ROWP + c) * 2);
                LDSM4(bh1, smb + (uint32_t)(OFF_BH + (rb0 + 16) * ROWP + c) * 2);
                LDSM4(bl0, smb + (uint32_t)(OFF_BL + rb0 * ROWP + c) * 2);
                LDSM4(bl1, smb + (uint32_t)(OFF_BL + (rb0 + 16) * ROWP + c) * 2);

                MMA16816(acc[0], ah, bh0[0], bh0[2]);
                MMA16816(acc[1], ah, bh0[1], bh0[3]);
                MMA16816(acc[2], ah, bh1[0], bh1[2]);
                MMA16816(acc[3], ah, bh1[1], bh1[3]);

                MMA16816(acc[0], al, bh0[0], bh0[2]);
                MMA16816(acc[1], al, bh0[1], bh0[3]);
                MMA16816(acc[2], al, bh1[0], bh1[2]);
                MMA16816(acc[3], al, bh1[1], bh1[3]);

                MMA16816(acc[0], ah, bl0[0], bl0[2]);
                MMA16816(acc[1], ah, bl0[1], bl0[3]);
                MMA16816(acc[2], ah, bl1[0], bl1[2]);
                MMA16816(acc[3], ah, bl1[1], bl1[3]);
            }

            float* P = g_part + (size_t)kz * (NM * NF);
            const int rbase = m0 + wm + (lane >> 2);
            const int cbase = f0 + wn + (lane & 3) * 2;
#pragma unroll
            for (int ni = 0; ni < 4; ni++) {
                int col = cbase + ni * 8;
                *(float2*)(P + (size_t)rbase * NF + col)       = make_float2(acc[ni][0], acc[ni][1]);
                *(float2*)(P + (size_t)(rbase + 8) * NF + col) = make_float2(acc[ni][2], acc[ni][3]);
            }
            __syncthreads();              // smem reuse guard (loop rarely repeats)
        }
    }

    grid_bar();

    // ================= Phase 3: reduce =================
    for (int i = tg; i < NM * NF / 4; i += NT) {
        float4 v = ((const float4*)bias)[i % (NF / 4)];
#pragma unroll
        for (int s = 0; s < SPLITS; s++) {
            float4 p = ((const float4*)g_part)[s * (NM * NF / 4) + i];
            v.x += p.x; v.y += p.y; v.z += p.z; v.w += p.w;
        }
        ((float4*)out)[i] = v;
    }
}

// ---------------------------------------------------------------------------
extern "C" void kernel_launch(void* const* d_in, const int* in_sizes, int n_in,
                              void* d_out, int out_size) {
    const float* x      = (const float*)d_in[0];
    const float* scale  = (const float*)d_in[1];
    const int*   binary = (const int*)  d_in[2];
    const float* bias   = (const float*)d_in[3];
    float*       out    = (float*)d_out;

    int dev = 0, sms = 0;
    cudaGetDevice(&dev);
    cudaDeviceGetAttribute(&sms, cudaDevAttrMultiProcessorCount, dev);
    if (sms <= 0) sms = 64;

    cudaFuncSetAttribute(fused_kernel,
                         cudaFuncAttributeMaxDynamicSharedMemorySize, SMEM_BYTES);

    fused_kernel<<<sms, 512, SMEM_BYTES>>>(x, scale, binary, bias, out);
}

// round 12
// speedup vs baseline: 1.1762x; 1.1762x over previous
#include <cuda_runtime.h>
#include <cuda_bf16.h>
#include <cstdint>

// out = x @ Weff + bias;  Weff[8m+p, f] = sum_k scale[k,f]*sign(bit(7-p) of binary[k,m,f])
// Two kernels:
//   prep: build bf16 hi/lo Weff^T ([f][k]) from binary*scale; split x -> Ah/Al;
//         seed out with bias.
//   gemm: 288 CTAs (12 f x 4 m x 6 k-splits), tile 64x64x128, fused 3-segment
//         HMMA (Ah*Bh + Al*Bh + Ah*Bl), epilogue red.global.add into out.

#define NX 768
#define NF 768
#define NM 256
#define NG 96

#define SPLITS 6
#define BKC 128
#define ROWP 136         // 128 + 8 halves pad -> conflict-free ldmatrix

__device__ __nv_bfloat16 g_ah[NM * NX];
__device__ __nv_bfloat16 g_al[NM * NX];
__device__ __nv_bfloat16 g_bh[NF * NX];   // [f][k]
__device__ __nv_bfloat16 g_bl[NF * NX];

// ---------------------------------------------------------------------------
union B2U { __nv_bfloat162 h2; uint32_t u; };
__device__ __forceinline__ uint32_t pk2(__nv_bfloat16 a, __nv_bfloat16 b) {
    B2U t; t.h2 = __halves2bfloat162(a, b); return t.u;
}
__device__ __forceinline__ uint32_t smem_u32(const void* p) {
    uint32_t a;
    asm("{ .reg .u64 t; cvta.to.shared.u64 t, %1; cvt.u32.u64 %0, t; }"
        : "=r"(a) : "l"(p));
    return a;
}
__device__ __forceinline__ void cp16(uint32_t s, const void* g) {
    asm volatile("cp.async.cg.shared.global [%0], [%1], 16;" :: "r"(s), "l"(g));
}

#define LDSM4(r, addr) \
    asm volatile("ldmatrix.sync.aligned.m8n8.x4.shared.b16 {%0,%1,%2,%3}, [%4];" \
                 : "=r"((r)[0]), "=r"((r)[1]), "=r"((r)[2]), "=r"((r)[3]) : "r"(addr))

#define MMA16816(c, a, bb0, bb1) \
    asm volatile("mma.sync.aligned.m16n8k16.row.col.f32.bf16.bf16.f32 " \
                 "{%0,%1,%2,%3}, {%4,%5,%6,%7}, {%8,%9}, {%0,%1,%2,%3};" \
                 : "+f"((c)[0]), "+f"((c)[1]), "+f"((c)[2]), "+f"((c)[3]) \
                 : "r"((a)[0]), "r"((a)[1]), "r"((a)[2]), "r"((a)[3]), \
                   "r"(bb0), "r"(bb1))

// ---------------------------------------------------------------------------
// Kernel 1 (prep): blocks [0,288) build Bh/Bl; [288,480) split x -> Ah/Al;
// [480,672) seed out with bias.
// ---------------------------------------------------------------------------
__global__ __launch_bounds__(256)
void prep_kernel(const float* __restrict__ scale,
                 const int*   __restrict__ binary,
                 const float* __restrict__ x,
                 const float* __restrict__ bias,
                 float*       __restrict__ out) {
    const int b = blockIdx.x, tid = threadIdx.x;

    if (b < 288) {                       // ---- build Weff -> bf16 hi/lo ----
        const int t = b * 256 + tid;     // < 73728 = NG*NF
        const int f = t % NF;            // coalesced
        const int m = t / NF;

        int   c[8];
        float s[8];
#pragma unroll
        for (int k = 0; k < 8; k++) {
            c[k] = binary[(k * NG + m) * NF + f];
            s[k] = scale[k * NF + f];
        }
        float w[8];
#pragma unroll
        for (int p = 0; p < 8; p++) w[p] = 0.0f;
#pragma unroll
        for (int k = 0; k < 8; k++)
#pragma unroll
            for (int p = 0; p < 8; p++)
                w[p] += ((c[k] >> (7 - p)) & 1) ? s[k] : -s[k];

        __nv_bfloat16 hi[8], lo[8];
#pragma unroll
        for (int p = 0; p < 8; p++) {
            hi[p] = __float2bfloat16(w[p]);
            lo[p] = __float2bfloat16(w[p] - __bfloat162float(hi[p]));
        }
        *(uint4*)(g_bh + (size_t)f * NX + 8 * m) =
            make_uint4(pk2(hi[0], hi[1]), pk2(hi[2], hi[3]),
                       pk2(hi[4], hi[5]), pk2(hi[6], hi[7]));
        *(uint4*)(g_bl + (size_t)f * NX + 8 * m) =
            make_uint4(pk2(lo[0], lo[1]), pk2(lo[2], lo[3]),
                       pk2(lo[4], lo[5]), pk2(lo[6], lo[7]));
    } else if (b < 480) {                // ---- split x -> Ah/Al ----
        const int i = (b - 288) * 256 + tid;   // < 49152 = NM*NX/4
        float4 v = ((const float4*)x)[i];
        __nv_bfloat16 h0 = __float2bfloat16(v.x), h1 = __float2bfloat16(v.y);
        __nv_bfloat16 h2 = __float2bfloat16(v.z), h3 = __float2bfloat16(v.w);
        __nv_bfloat16 l0 = __float2bfloat16(v.x - __bfloat162float(h0));
        __nv_bfloat16 l1 = __float2bfloat16(v.y - __bfloat162float(h1));
        __nv_bfloat16 l2 = __float2bfloat16(v.z - __bfloat162float(h2));
        __nv_bfloat16 l3 = __float2bfloat16(v.w - __bfloat162float(h3));
        ((uint2*)g_ah)[i] = make_uint2(pk2(h0, h1), pk2(h2, h3));
        ((uint2*)g_al)[i] = make_uint2(pk2(l0, l1), pk2(l2, l3));
    } else {                             // ---- seed out with bias ----
        const int idx = (b - 480) * 256 + tid; // < 49152 = NM*NF/4
        ((float4*)out)[idx] = ((const float4*)bias)[idx % (NF / 4)];
    }
}

// ---------------------------------------------------------------------------
// Kernel 2: fused-segment HMMA GEMM, atomic epilogue into bias-seeded out.
// Grid (12 n, 4 m, 6 split) = 288 CTAs x 256 thr (8 warps, warp tile 16x32).
// ---------------------------------------------------------------------------
#define SM_T (64 * ROWP)
#define SMEM_BYTES (4 * SM_T * 2)    // 69632

__global__ __launch_bounds__(256)
void gemm_mma_kernel(float* __restrict__ out) {
    extern __shared__ __align__(16) __nv_bfloat16 sm[];

    const int tid  = threadIdx.x;
    const int wid  = tid >> 5;
    const int lane = tid & 31;

    const int f0 = blockIdx.x * 64;
    const int m0 = blockIdx.y * 64;
    const int k0 = blockIdx.z * BKC;

    const __nv_bfloat16* gAH = g_ah + (size_t)m0 * NX + k0;
    const __nv_bfloat16* gAL = g_al + (size_t)m0 * NX + k0;
    const __nv_bfloat16* gBH = g_bh + (size_t)f0 * NX + k0;
    const __nv_bfloat16* gBL = g_bl + (size_t)f0 * NX + k0;

    // load all four 64x128 tiles (16 cp.async x 16B per thread)
#pragma unroll
    for (int j = 0; j < 4; j++) {
        int idx = tid + 256 * j;         // 0..1023
        int r = idx >> 4, c8 = (idx & 15) * 8;
        size_t go = (size_t)r * NX + c8;
        uint32_t so = smem_u32(sm) + (uint32_t)(r * ROWP + c8) * 2;
        cp16(so,                gAH + go);
        cp16(so + SM_T * 2,     gAL + go);
        cp16(so + 2 * SM_T * 2, gBH + go);
        cp16(so + 3 * SM_T * 2, gBL + go);
    }
    asm volatile("cp.async.commit_group;" ::: "memory");

    const int wm = (wid >> 1) * 16;   // 4 warps along m
    const int wn = (wid & 1) * 32;    // 2 warps along n

    float acc[4][4];
#pragma unroll
    for (int j = 0; j < 4; j++)
#pragma unroll
        for (int v = 0; v < 4; v++) acc[j][v] = 0.0f;

    asm volatile("cp.async.wait_group 0;" ::: "memory");
    __syncthreads();

    const int ra  = wm + (lane & 15);
    const int rb0 = wn + (lane & 15);
    const uint32_t smb = smem_u32(sm);

#pragma unroll
    for (int ks = 0; ks < 8; ks++) {
        const int c = ks * 16 + ((lane >> 4) << 3);
        uint32_t ah[4], al[4], bh0[4], bh1[4], bl0[4], bl1[4];
        LDSM4(ah,  smb + (uint32_t)(ra * ROWP + c) * 2);
        LDSM4(al,  smb + (uint32_t)(SM_T + ra * ROWP + c) * 2);
        LDSM4(bh0, smb + (uint32_t)(2 * SM_T + rb0 * ROWP + c) * 2);
        LDSM4(bh1, smb + (uint32_t)(2 * SM_T + (rb0 + 16) * ROWP + c) * 2);
        LDSM4(bl0, smb + (uint32_t)(3 * SM_T + rb0 * ROWP + c) * 2);
        LDSM4(bl1, smb + (uint32_t)(3 * SM_T + (rb0 + 16) * ROWP + c) * 2);

        MMA16816(acc[0], ah, bh0[0], bh0[2]);
        MMA16816(acc[1], ah, bh0[1], bh0[3]);
        MMA16816(acc[2], ah, bh1[0], bh1[2]);
        MMA16816(acc[3], ah, bh1[1], bh1[3]);

        MMA16816(acc[0], al, bh0[0], bh0[2]);
        MMA16816(acc[1], al, bh0[1], bh0[3]);
        MMA16816(acc[2], al, bh1[0], bh1[2]);
        MMA16816(acc[3], al, bh1[1], bh1[3]);

        MMA16816(acc[0], ah, bl0[0], bl0[2]);
        MMA16816(acc[1], ah, bl0[1], bl0[3]);
        MMA16816(acc[2], ah, bl1[0], bl1[2]);
        MMA16816(acc[3], ah, bl1[1], bl1[3]);
    }

    // ---- epilogue: accumulate into bias-seeded out (no partials, no reduce) ----
    const int rbase = m0 + wm + (lane >> 2);
    const int cbase = f0 + wn + (lane & 3) * 2;
#pragma unroll
    for (int ni = 0; ni < 4; ni++) {
        int col = cbase + ni * 8;
        float* p0 = out + (size_t)rbase * NF + col;
        float* p1 = out + (size_t)(rbase + 8) * NF + col;
        asm volatile("red.global.add.v2.f32 [%0], {%1, %2};"
                     :: "l"(p0), "f"(acc[ni][0]), "f"(acc[ni][1]) : "memory");
        asm volatile("red.global.add.v2.f32 [%0], {%1, %2};"
                     :: "l"(p1), "f"(acc[ni][2]), "f"(acc[ni][3]) : "memory");
    }
}

// ---------------------------------------------------------------------------
extern "C" void kernel_launch(void* const* d_in, const int* in_sizes, int n_in,
                              void* d_out, int out_size) {
    const float* x      = (const float*)d_in[0];
    const float* scale  = (const float*)d_in[1];
    const int*   binary = (const int*)  d_in[2];
    const float* bias   = (const float*)d_in[3];
    float*       out    = (float*)d_out;

    cudaFuncSetAttribute(gemm_mma_kernel,
                         cudaFuncAttributeMaxDynamicSharedMemorySize, SMEM_BYTES);

    prep_kernel<<<672, 256>>>(scale, binary, x, bias, out);

    dim3 grid(NF / 64, NM / 64, SPLITS);   // 12 x 4 x 6 = 288 CTAs
    gemm_mma_kernel<<<grid, 256, SMEM_BYTES>>>(out);
}

// round 13
// speedup vs baseline: 1.3351x; 1.1351x over previous
#include <cuda_runtime.h>
#include <cuda_bf16.h>
#include <cstdint>

// out = x @ Weff + bias;  Weff[8m+p, f] = sum_k scale[k,f]*sign(bit(7-p) of binary[k,m,f])
// Two kernels:
//   prep: build bf16 hi/lo Weff^T ([f][k]); split x -> Ah/Al; seed out with bias.
//   gemm: 144 CTAs (12 f x 4 m x 3 k-splits), tile 64x64, K=256/CTA as 4x64
//         double-buffered chunks; fused 3-segment HMMA; red.global.add epilogue.

#define NX 768
#define NF 768
#define NM 256
#define NG 96

#define SPLITS 3
#define KCTA 256          // k per CTA
#define NCH 4             // chunks of 64
#define ROWK 72           // 64 + 8 halves pad (144B rows) -> conflict-free ldmatrix

__device__ __nv_bfloat16 g_ah[NM * NX];
__device__ __nv_bfloat16 g_al[NM * NX];
__device__ __nv_bfloat16 g_bh[NF * NX];   // [f][k]
__device__ __nv_bfloat16 g_bl[NF * NX];

// ---------------------------------------------------------------------------
union B2U { __nv_bfloat162 h2; uint32_t u; };
__device__ __forceinline__ uint32_t pk2(__nv_bfloat16 a, __nv_bfloat16 b) {
    B2U t; t.h2 = __halves2bfloat162(a, b); return t.u;
}
__device__ __forceinline__ uint32_t smem_u32(const void* p) {
    uint32_t a;
    asm("{ .reg .u64 t; cvta.to.shared.u64 t, %1; cvt.u32.u64 %0, t; }"
        : "=r"(a) : "l"(p));
    return a;
}
__device__ __forceinline__ void cp16(uint32_t s, const void* g) {
    asm volatile("cp.async.cg.shared.global [%0], [%1], 16;" :: "r"(s), "l"(g));
}

#define LDSM4(r, addr) \
    asm volatile("ldmatrix.sync.aligned.m8n8.x4.shared.b16 {%0,%1,%2,%3}, [%4];" \
                 : "=r"((r)[0]), "=r"((r)[1]), "=r"((r)[2]), "=r"((r)[3]) : "r"(addr))

#define MMA16816(c, a, bb0, bb1) \
    asm volatile("mma.sync.aligned.m16n8k16.row.col.f32.bf16.bf16.f32 " \
                 "{%0,%1,%2,%3}, {%4,%5,%6,%7}, {%8,%9}, {%0,%1,%2,%3};" \
                 : "+f"((c)[0]), "+f"((c)[1]), "+f"((c)[2]), "+f"((c)[3]) \
                 : "r"((a)[0]), "r"((a)[1]), "r"((a)[2]), "r"((a)[3]), \
                   "r"(bb0), "r"(bb1))

// ---------------------------------------------------------------------------
// Kernel 1 (prep): [0,288) build Bh/Bl; [288,480) split x; [480,672) seed bias.
// ---------------------------------------------------------------------------
__global__ __launch_bounds__(256)
void prep_kernel(const float* __restrict__ scale,
                 const int*   __restrict__ binary,
                 const float* __restrict__ x,
                 const float* __restrict__ bias,
                 float*       __restrict__ out) {
    const int b = blockIdx.x, tid = threadIdx.x;

    if (b < 288) {
        const int t = b * 256 + tid;     // < 73728 = NG*NF
        const int f = t % NF;
        const int m = t / NF;

        int   c[8];
        float s[8];
#pragma unroll
        for (int k = 0; k < 8; k++) {
            c[k] = binary[(k * NG + m) * NF + f];
            s[k] = scale[k * NF + f];
        }
        float w[8];
#pragma unroll
        for (int p = 0; p < 8; p++) w[p] = 0.0f;
#pragma unroll
        for (int k = 0; k < 8; k++)
#pragma unroll
            for (int p = 0; p < 8; p++)
                w[p] += ((c[k] >> (7 - p)) & 1) ? s[k] : -s[k];

        __nv_bfloat16 hi[8], lo[8];
#pragma unroll
        for (int p = 0; p < 8; p++) {
            hi[p] = __float2bfloat16(w[p]);
            lo[p] = __float2bfloat16(w[p] - __bfloat162float(hi[p]));
        }
        *(uint4*)(g_bh + (size_t)f * NX + 8 * m) =
            make_uint4(pk2(hi[0], hi[1]), pk2(hi[2], hi[3]),
                       pk2(hi[4], hi[5]), pk2(hi[6], hi[7]));
        *(uint4*)(g_bl + (size_t)f * NX + 8 * m) =
            make_uint4(pk2(lo[0], lo[1]), pk2(lo[2], lo[3]),
                       pk2(lo[4], lo[5]), pk2(lo[6], lo[7]));
    } else if (b < 480) {
        const int i = (b - 288) * 256 + tid;   // < 49152 = NM*NX/4
        float4 v = ((const float4*)x)[i];
        __nv_bfloat16 h0 = __float2bfloat16(v.x), h1 = __float2bfloat16(v.y);
        __nv_bfloat16 h2 = __float2bfloat16(v.z), h3 = __float2bfloat16(v.w);
        __nv_bfloat16 l0 = __float2bfloat16(v.x - __bfloat162float(h0));
        __nv_bfloat16 l1 = __float2bfloat16(v.y - __bfloat162float(h1));
        __nv_bfloat16 l2 = __float2bfloat16(v.z - __bfloat162float(h2));
        __nv_bfloat16 l3 = __float2bfloat16(v.w - __bfloat162float(h3));
        ((uint2*)g_ah)[i] = make_uint2(pk2(h0, h1), pk2(h2, h3));
        ((uint2*)g_al)[i] = make_uint2(pk2(l0, l1), pk2(l2, l3));
    } else {
        const int idx = (b - 480) * 256 + tid; // < 49152 = NM*NF/4
        ((float4*)out)[idx] = ((const float4*)bias)[idx % (NF / 4)];
    }
}

// ---------------------------------------------------------------------------
// Kernel 2: pipelined fused-segment HMMA GEMM, atomic epilogue.
// Grid (12, 4, 3) = 144 CTAs x 256 thr (8 warps, warp tile 16x32).
// smem: 2 buffers x (AH|AL|BH|BL), each tile 64 x ROWK halves.
// ---------------------------------------------------------------------------
#define SM_TK  (64 * ROWK)           // 4608 halves per tile
#define BUFH   (4 * SM_TK)           // 18432 halves per buffer
#define SMEM_BYTES (2 * BUFH * 2)    // 73728 bytes

__global__ __launch_bounds__(256)
void gemm_mma_kernel(float* __restrict__ out) {
    extern __shared__ __align__(16) __nv_bfloat16 sm[];

    const int tid  = threadIdx.x;
    const int wid  = tid >> 5;
    const int lane = tid & 31;

    const int f0 = blockIdx.x * 64;
    const int m0 = blockIdx.y * 64;
    const int k0 = blockIdx.z * KCTA;

    const __nv_bfloat16* gAH = g_ah + (size_t)m0 * NX + k0;
    const __nv_bfloat16* gAL = g_al + (size_t)m0 * NX + k0;
    const __nv_bfloat16* gBH = g_bh + (size_t)f0 * NX + k0;
    const __nv_bfloat16* gBL = g_bl + (size_t)f0 * NX + k0;

    const uint32_t smb = smem_u32(sm);

    // loader: chunk ci (64 k) -> buffer b. 2048 cp16 total, 8 per thread.
    auto load_chunk = [&](int ci, int b) {
        const int kc = ci * 64;
        const uint32_t sb = smb + (uint32_t)(b * BUFH) * 2;
#pragma unroll
        for (int j = 0; j < 2; j++) {
            int idx = tid + 256 * j;           // 0..511
            int r = idx >> 3, c8 = (idx & 7) * 8;
            size_t go = (size_t)r * NX + kc + c8;
            uint32_t so = sb + (uint32_t)(r * ROWK + c8) * 2;
            cp16(so,               gAH + go);
            cp16(so + SM_TK * 2,   gAL + go);
            cp16(so + 2 * SM_TK * 2, gBH + go);
            cp16(so + 3 * SM_TK * 2, gBL + go);
        }
        asm volatile("cp.async.commit_group;" ::: "memory");
    };

    load_chunk(0, 0);
    load_chunk(1, 1);

    const int wm = (wid >> 1) * 16;   // 4 warps along m
    const int wn = (wid & 1) * 32;    // 2 warps along n

    float acc[4][4];
#pragma unroll
    for (int j = 0; j < 4; j++)
#pragma unroll
        for (int v = 0; v < 4; v++) acc[j][v] = 0.0f;

    const int ra  = wm + (lane & 15);
    const int rb0 = wn + (lane & 15);

#pragma unroll
    for (int i = 0; i < NCH; i++) {
        if (i < NCH - 1) asm volatile("cp.async.wait_group 1;" ::: "memory");
        else             asm volatile("cp.async.wait_group 0;" ::: "memory");
        __syncthreads();

        const uint32_t sb = smb + (uint32_t)((i & 1) * BUFH) * 2;
#pragma unroll
        for (int ks = 0; ks < 4; ks++) {
            const int c = ks * 16 + ((lane >> 4) << 3);
            uint32_t ah[4], al[4], bh0[4], bh1[4], bl0[4], bl1[4];
            LDSM4(ah,  sb + (uint32_t)(ra * ROWK + c) * 2);
            LDSM4(al,  sb + (uint32_t)(SM_TK + ra * ROWK + c) * 2);
            LDSM4(bh0, sb + (uint32_t)(2 * SM_TK + rb0 * ROWK + c) * 2);
            LDSM4(bh1, sb + (uint32_t)(2 * SM_TK + (rb0 + 16) * ROWK + c) * 2);
            LDSM4(bl0, sb + (uint32_t)(3 * SM_TK + rb0 * ROWK + c) * 2);
            LDSM4(bl1, sb + (uint32_t)(3 * SM_TK + (rb0 + 16) * ROWK + c) * 2);

            MMA16816(acc[0], ah, bh0[0], bh0[2]);
            MMA16816(acc[1], ah, bh0[1], bh0[3]);
            MMA16816(acc[2], ah, bh1[0], bh1[2]);
            MMA16816(acc[3], ah, bh1[1], bh1[3]);

            MMA16816(acc[0], al, bh0[0], bh0[2]);
            MMA16816(acc[1], al, bh0[1], bh0[3]);
            MMA16816(acc[2], al, bh1[0], bh1[2]);
            MMA16816(acc[3], al, bh1[1], bh1[3]);

            MMA16816(acc[0], ah, bl0[0], bl0[2]);
            MMA16816(acc[1], ah, bl0[1], bl0[3]);
            MMA16816(acc[2], ah, bl1[0], bl1[2]);
            MMA16816(acc[3], ah, bl1[1], bl1[3]);
        }
        __syncthreads();                  // all warps done reading buf (i&1)

        if (i + 2 < NCH) load_chunk(i + 2, i & 1);
    }

    // ---- epilogue: accumulate into bias-seeded out ----
    const int rbase = m0 + wm + (lane >> 2);
    const int cbase = f0 + wn + (lane & 3) * 2;
#pragma unroll
    for (int ni = 0; ni < 4; ni++) {
        int col = cbase + ni * 8;
        float* p0 = out + (size_t)rbase * NF + col;
        float* p1 = out + (size_t)(rbase + 8) * NF + col;
        asm volatile("red.global.add.v2.f32 [%0], {%1, %2};"
                     :: "l"(p0), "f"(acc[ni][0]), "f"(acc[ni][1]) : "memory");
        asm volatile("red.global.add.v2.f32 [%0], {%1, %2};"
                     :: "l"(p1), "f"(acc[ni][2]), "f"(acc[ni][3]) : "memory");
    }
}

// ---------------------------------------------------------------------------
extern "C" void kernel_launch(void* const* d_in, const int* in_sizes, int n_in,
                              void* d_out, int out_size) {
    const float* x      = (const float*)d_in[0];
    const float* scale  = (const float*)d_in[1];
    const int*   binary = (const int*)  d_in[2];
    const float* bias   = (const float*)d_in[3];
    float*       out    = (float*)d_out;

    cudaFuncSetAttribute(gemm_mma_kernel,
                         cudaFuncAttributeMaxDynamicSharedMemorySize, SMEM_BYTES);

    prep_kernel<<<672, 256>>>(scale, binary, x, bias, out);

    dim3 grid(NF / 64, NM / 64, SPLITS);   // 12 x 4 x 3 = 144 CTAs
    gemm_mma_kernel<<<grid, 256, SMEM_BYTES>>>(out);
}